// round 1
// baseline (speedup 1.0000x reference)
#include <cuda_runtime.h>

// Problem: inputs [8,128,128,64] f32, beta [64,16] f32
// out[e, c] = inputs[e] * u[e%64, c],  u = beta^2 / rowsum(beta^2)
// out is [8*128*128*64, 16] f32 contiguous.

#define D_DIM 64
#define C_DIM 16

__device__ float d_u[D_DIM * C_DIM];  // 1024 floats, scratch (no alloc allowed)

// One block, 64 threads: each thread normalizes one row of beta^2.
__global__ void compute_u_kernel(const float* __restrict__ beta) {
    int i = threadIdx.x;  // 0..63
    float b[C_DIM];
    float s = 0.0f;
#pragma unroll
    for (int c = 0; c < C_DIM; ++c) {
        float v = beta[i * C_DIM + c];
        b[c] = v * v;
        s += b[c];
    }
    float inv = 1.0f / s;
#pragma unroll
    for (int c = 0; c < C_DIM; ++c) {
        d_u[i * C_DIM + c] = b[c] * inv;
    }
}

// One thread per output float4 (16 bytes). g = global float4 index.
//   input element e = g >> 2, row i = e & 63, quarter j = g & 3.
// Consecutive threads -> consecutive 16B stores -> full 128B/warp coalescing.
__global__ void __launch_bounds__(256) broadcast_mul_kernel(
    const float* __restrict__ in, float4* __restrict__ out, unsigned int n4) {
    __shared__ float4 su[D_DIM * 4];  // u as 256 float4 = 4 KiB

    su[threadIdx.x] = reinterpret_cast<const float4*>(d_u)[threadIdx.x];
    __syncthreads();

    unsigned int g = blockIdx.x * 256u + threadIdx.x;
    if (g >= n4) return;

    unsigned int e = g >> 2;          // input element index
    unsigned int j = g & 3u;          // which float4 of the 16 outputs
    unsigned int i = e & (D_DIM - 1); // row into u

    float x = __ldg(in + e);
    float4 u = su[i * 4 + j];
    out[g] = make_float4(x * u.x, x * u.y, x * u.z, x * u.w);
}

extern "C" void kernel_launch(void* const* d_in, const int* in_sizes, int n_in,
                              void* d_out, int out_size) {
    const float* inputs = (const float*)d_in[0];  // 8*128*128*64 = 8388608
    const float* beta   = (const float*)d_in[1];  // 64*16 = 1024
    float4* out = (float4*)d_out;

    compute_u_kernel<<<1, D_DIM>>>(beta);

    unsigned int n4 = (unsigned int)(out_size / 4);  // 33,554,432 float4s
    unsigned int blocks = (n4 + 255u) / 256u;        // 131072
    broadcast_mul_kernel<<<blocks, 256>>>(inputs, out, n4);
}

// round 2
// speedup vs baseline: 1.1123x; 1.1123x over previous
#include <cuda_runtime.h>

// Problem: inputs [8,128,128,64] f32, beta [64,16] f32
// out[e, c] = inputs[e] * u[e%64, c],  u = beta^2 / rowsum(beta^2)
// out flat: n4 = 2^25 float4s. (i,j) pattern has period 256 in float4 index.

#define D_DIM 64
#define C_DIM 16

__device__ float d_u[D_DIM * C_DIM];  // 4 KiB scratch (no allocs allowed)

__global__ void compute_u_kernel(const float* __restrict__ beta) {
    int i = threadIdx.x;  // 0..63
    float b[C_DIM];
    float s = 0.0f;
#pragma unroll
    for (int c = 0; c < C_DIM; ++c) {
        float v = beta[i * C_DIM + c];
        b[c] = v * v;
        s += b[c];
    }
    float inv = 1.0f / s;
#pragma unroll
    for (int c = 0; c < C_DIM; ++c) {
        d_u[i * C_DIM + c] = b[c] * inv;
    }
}

// Grid-stride with stride = BLOCKS*256 (multiple of 256) => each thread's
// (i = (g>>2)&63, j = g&3) is loop-invariant => u float4 lives in registers.
// BLOCKS=1024, THREADS=256: 2^18 threads, n4=2^25 => exactly 128 iters,
// no bounds checks, single wave on 148 SMs.
#define BLOCKS 1024
#define THREADS 256
#define ITERS 128  // n4 / (BLOCKS*THREADS)

__global__ void __launch_bounds__(THREADS) broadcast_mul_kernel(
    const float* __restrict__ in, float4* __restrict__ out) {
    unsigned int g = blockIdx.x * THREADS + threadIdx.x;
    unsigned int i = (g >> 2) & (D_DIM - 1);
    unsigned int j = g & 3u;

    const float4 u = __ldg(reinterpret_cast<const float4*>(d_u) + i * 4 + j);

    const unsigned int stride = BLOCKS * THREADS;  // 2^19

#pragma unroll 4
    for (int it = 0; it < ITERS; ++it) {
        float x = __ldcs(in + (g >> 2));
        float4 r = make_float4(x * u.x, x * u.y, x * u.z, x * u.w);
        __stcs(out + g, r);
        g += stride;
    }
}

extern "C" void kernel_launch(void* const* d_in, const int* in_sizes, int n_in,
                              void* d_out, int out_size) {
    const float* inputs = (const float*)d_in[0];  // 8*128*128*64 = 8388608
    const float* beta   = (const float*)d_in[1];  // 64*16 = 1024
    float4* out = (float4*)d_out;

    compute_u_kernel<<<1, D_DIM>>>(beta);
    broadcast_mul_kernel<<<BLOCKS, THREADS>>>(inputs, out);
}

// round 3
// speedup vs baseline: 1.3390x; 1.2038x over previous
#include <cuda_runtime.h>

// Problem: inputs [8,128,128,64] f32, beta [64,16] f32
// out[e, c] = inputs[e] * u[e%64, c],  u = beta^2 / rowsum(beta^2)
// out flat: n4 = 2^25 float4s. (i = (g>>2)&63, j = g&3) has period 256 in g,
// and the grid stride is a multiple of 256 -> per-thread u is loop-invariant.

#define D_DIM 64
#define BLOCKS 1024
#define THREADS 256
#define STRIDE (BLOCKS * THREADS)      // 2^18 float4s per grid step
#define ITERS 128                      // 2^25 / STRIDE
#define UNROLL 8

__global__ void __launch_bounds__(THREADS) fused_broadcast_mul(
    const float* __restrict__ in, const float* __restrict__ beta,
    float4* __restrict__ out) {
    unsigned int g = blockIdx.x * THREADS + threadIdx.x;
    unsigned int i = (g >> 2) & (D_DIM - 1);  // beta row
    unsigned int j = g & 3u;                  // which float4 quarter of the row

    // ---- compute this thread's u quarter in registers (one-time prologue) ----
    const float4* br = reinterpret_cast<const float4*>(beta) + i * 4;
    float4 q0 = __ldg(br + 0);
    float4 q1 = __ldg(br + 1);
    float4 q2 = __ldg(br + 2);
    float4 q3 = __ldg(br + 3);
    float s = q0.x * q0.x + q0.y * q0.y + q0.z * q0.z + q0.w * q0.w
            + q1.x * q1.x + q1.y * q1.y + q1.z * q1.z + q1.w * q1.w
            + q2.x * q2.x + q2.y * q2.y + q2.z * q2.z + q2.w * q2.w
            + q3.x * q3.x + q3.y * q3.y + q3.z * q3.z + q3.w * q3.w;
    float inv = 1.0f / s;
    float4 bq = (j == 0) ? q0 : (j == 1) ? q1 : (j == 2) ? q2 : q3;
    const float4 u = make_float4(bq.x * bq.x * inv, bq.y * bq.y * inv,
                                 bq.z * bq.z * inv, bq.w * bq.w * inv);

    // ---- streaming loop: batch UNROLL independent loads, then stores ----
    const float* ip = in + (g >> 2);
    float4* op = out + g;

    for (int it = 0; it < ITERS / UNROLL; ++it) {
        float x[UNROLL];
#pragma unroll
        for (int k = 0; k < UNROLL; ++k)
            x[k] = __ldg(ip + k * (STRIDE / 4));   // L2-resident reads
#pragma unroll
        for (int k = 0; k < UNROLL; ++k) {
            float4 r = make_float4(x[k] * u.x, x[k] * u.y,
                                   x[k] * u.z, x[k] * u.w);
            __stcs(op + k * STRIDE, r);            // evict-first write stream
        }
        ip += (STRIDE / 4) * UNROLL;
        op += STRIDE * UNROLL;
    }
}

extern "C" void kernel_launch(void* const* d_in, const int* in_sizes, int n_in,
                              void* d_out, int out_size) {
    const float* inputs = (const float*)d_in[0];  // 8*128*128*64 = 8388608
    const float* beta   = (const float*)d_in[1];  // 64*16 = 1024
    float4* out = (float4*)d_out;

    fused_broadcast_mul<<<BLOCKS, THREADS>>>(inputs, beta, out);
}